// round 13
// baseline (speedup 1.0000x reference)
#include <cuda_runtime.h>
#include <cuda_bf16.h>
#include <cstdint>

#define Bsz 4096
#define Dd  66
#define Hh  512
#define K1P 128      // padded K for layer 1 (66 + 1 + zeros)

// tcgen05 is arch-specific: only emit it in the sm_103a (or sm_100a) pass.
#if defined(__CUDA_ARCH_FEAT_SM103_ALL) || defined(__CUDA_ARCH_FEAT_SM100_ALL) || \
    (defined(__CUDA_ARCH_SPECIFIC__) && defined(__CUDA_ARCH__) && (__CUDA_ARCH__ >= 1000))
#define HAS_TCGEN05 1
#else
#define HAS_TCGEN05 0
#endif

typedef __nv_bfloat16 bf16;

// ---------------- scratch (__device__ globals; allocation-free rule) ---------
__device__ bf16  g_A0h[Bsz*K1P], g_A0l[Bsz*K1P];
__device__ bf16  g_W1h[Hh*K1P],  g_W1l[Hh*K1P];     // W1^T padded [512 x 128]
__device__ bf16  g_W2h[Hh*Hh],   g_W2l[Hh*Hh];      // W2^T [512 x 512]
__device__ bf16  g_W3h[128*Hh],  g_W3l[128*Hh];     // W3^T padded [128 x 512]
__device__ bf16  g_Chb[Hh*Hh],   g_Clb[Hh*Hh];      // C^T  [512 x 512]
__device__ bf16  g_h1h[Bsz*Hh],  g_h1l[Bsz*Hh];
__device__ bf16  g_s1h[Bsz*Hh],  g_s1l[Bsz*Hh];
__device__ bf16  g_h2h[Bsz*Hh],  g_h2l[Bsz*Hh];
__device__ float g_s2[Bsz*Hh];
__device__ float g_dp[4*Bsz];
__device__ float g_l3p[4*Bsz*Dd];   // layer-3 K-split partials

// ---------------- helpers ----------------------------------------------------
__device__ __forceinline__ uint32_t smem_u32(const void* p) {
    uint32_t a;
    asm("{ .reg .u64 t; cvta.to.shared.u64 t, %1; cvt.u32.u64 %0, t; }" : "=r"(a) : "l"(p));
    return a;
}
__device__ __forceinline__ uint32_t sw128(uint32_t o) { return o ^ ((o >> 3) & 0x70); }
__device__ __forceinline__ void split2(float v, bf16& h, bf16& l) {
    h = __float2bfloat16(v);
    l = __float2bfloat16(v - __bfloat162float(h));
}

#if HAS_TCGEN05
__device__ __forceinline__ uint32_t elect_one() {
    uint32_t p;
    asm volatile("{\n\t.reg .pred p;\n\telect.sync _|p, 0xFFFFFFFF;\n\t"
                 "selp.b32 %0, 1, 0, p;\n\t}" : "=r"(p));
    return p;
}
__device__ __forceinline__ uint64_t mkdesc(uint32_t addr) {
    // SW128, version=1(Blackwell), SBO=64, LBO=1
    return 0x4000404000010000ull | ((uint64_t)(addr >> 4) & 0x3FFF);
}
__device__ __forceinline__ void mma_bf16_ss(uint32_t d, uint64_t ad, uint64_t bd,
                                            uint32_t idesc, uint32_t en) {
    asm volatile("{\n\t.reg .pred p;\n\tsetp.ne.u32 p, %4, 0;\n\t"
        "tcgen05.mma.cta_group::1.kind::f16 [%0], %1, %2, %3, {%5,%5,%5,%5}, p;\n\t}"
        :: "r"(d), "l"(ad), "l"(bd), "r"(idesc), "r"(en), "r"(0u) : "memory");
}
#define TCALLOC(sp, n)  asm volatile("tcgen05.alloc.cta_group::1.sync.aligned.shared::cta.b32 [%0], %1;" :: "r"(sp), "r"(n) : "memory")
#define TCDEALLOC(t, n) asm volatile("tcgen05.dealloc.cta_group::1.sync.aligned.b32 %0, %1;" :: "r"(t), "r"(n))
#define TCRELINQ()      asm volatile("tcgen05.relinquish_alloc_permit.cta_group::1.sync.aligned;")
#define TCCOMMIT(mb)    asm volatile("tcgen05.commit.cta_group::1.mbarrier::arrive::one.shared::cluster.b64 [%0];" :: "r"(mb) : "memory")
#define MBINIT(mb, n)   asm volatile("mbarrier.init.shared.b64 [%0], %1;" :: "r"(mb), "r"(n) : "memory")
#define FENCE_ASYNC()   asm volatile("fence.proxy.async.shared::cta;" ::: "memory")
#define TCFENCE_AFTER() asm volatile("tcgen05.fence::after_thread_sync;" ::: "memory")
#define TCFENCE_BEFORE() asm volatile("tcgen05.fence::before_thread_sync;" ::: "memory")
#define TCWAIT_LD()     asm volatile("tcgen05.wait::ld.sync.aligned;" ::: "memory")

__device__ __forceinline__ void mbar_wait(uint32_t mb, uint32_t parity) {
    uint32_t done;
    asm volatile("{\n\t.reg .pred p;\n\t"
        "mbarrier.try_wait.parity.acquire.cta.shared::cta.b64 p, [%1], %2;\n\t"
        "selp.b32 %0, 1, 0, p;\n\t}" : "=r"(done) : "r"(mb), "r"(parity) : "memory");
    if (!done) {
        asm volatile("{\n\t.reg .pred P1;\n\tWL_%=:\n\t"
            "mbarrier.try_wait.parity.acquire.cta.shared::cta.b64 P1, [%0], %1, 0x989680;\n\t"
            "@P1 bra.uni WD_%=;\n\tbra.uni WL_%=;\n\tWD_%=:\n\t}"
            :: "r"(mb), "r"(parity) : "memory");
    }
}
#define LDTM32(r, a) \
    asm volatile("tcgen05.ld.sync.aligned.32x32b.x32.b32 " \
        "{%0,%1,%2,%3,%4,%5,%6,%7,%8,%9,%10,%11,%12,%13,%14,%15," \
        "%16,%17,%18,%19,%20,%21,%22,%23,%24,%25,%26,%27,%28,%29,%30,%31}, [%32];" \
        : "=r"((r)[0]),"=r"((r)[1]),"=r"((r)[2]),"=r"((r)[3]),"=r"((r)[4]),"=r"((r)[5]), \
          "=r"((r)[6]),"=r"((r)[7]),"=r"((r)[8]),"=r"((r)[9]),"=r"((r)[10]),"=r"((r)[11]), \
          "=r"((r)[12]),"=r"((r)[13]),"=r"((r)[14]),"=r"((r)[15]),"=r"((r)[16]),"=r"((r)[17]), \
          "=r"((r)[18]),"=r"((r)[19]),"=r"((r)[20]),"=r"((r)[21]),"=r"((r)[22]),"=r"((r)[23]), \
          "=r"((r)[24]),"=r"((r)[25]),"=r"((r)[26]),"=r"((r)[27]),"=r"((r)[28]),"=r"((r)[29]), \
          "=r"((r)[30]),"=r"((r)[31]) : "r"(a))
#endif  // HAS_TCGEN05

// ---------------- prep kernels ----------------------------------------------
// Fused: C[i,j] = W2[i,j]*sum_d W3[j,d]*W1[d,i], written directly transposed+split:
// Chb/Clb[j*Hh + i].  grid (16,16), block (32,8). All global accesses coalesced.
__global__ void prep_C(const float* __restrict__ W1, const float* __restrict__ W2,
                       const float* __restrict__ W3,
                       bf16* __restrict__ Chb, bf16* __restrict__ Clb) {
    __shared__ float W2s[32][33];
    __shared__ float W3s[32][Dd];
    const int i0 = blockIdx.x * 32, j0 = blockIdx.y * 32;
    const int tx = threadIdx.x, ty = threadIdx.y;
#pragma unroll
    for (int r = 0; r < 4; r++)
        W2s[ty * 4 + r][tx] = W2[(size_t)(i0 + ty * 4 + r) * Hh + j0 + tx];
    for (int e = ty * 32 + tx; e < 32 * Dd; e += 256)
        W3s[e / Dd][e % Dd] = W3[(size_t)(j0 + e / Dd) * Dd + e % Dd];
    __syncthreads();
#pragma unroll
    for (int q = 0; q < 4; q++) {
        const int jl = ty * 4 + q;
        float acc = 0.f;
#pragma unroll
        for (int d = 0; d < Dd; d++)
            acc = fmaf(W3s[jl][d], W1[(size_t)d * Hh + i0 + tx], acc);
        float cv = W2s[tx][jl] * acc;
        bf16 h, l; split2(cv, h, l);
        Chb[(size_t)(j0 + jl) * Hh + i0 + tx] = h;
        Clb[(size_t)(j0 + jl) * Hh + i0 + tx] = l;
    }
}

// transpose + bf16 split body: out[n*KP+k] = split(W[k*NW+n]), zero-padded
__device__ __forceinline__ void conv_T_body(const float* __restrict__ W,
                                            bf16* __restrict__ oh, bf16* __restrict__ ol,
                                            int KS, int NS, int NW, int KP) {
    __shared__ float tile[32][33];
    int k0 = blockIdx.x * 32, n0 = blockIdx.y * 32;
    int tx = threadIdx.x, ty = threadIdx.y;
#pragma unroll
    for (int i = 0; i < 32; i += 8) {
        int k = k0 + ty + i, n = n0 + tx;
        tile[ty + i][tx] = (k < KS && n < NS) ? W[(size_t)k * NW + n] : 0.f;
    }
    __syncthreads();
#pragma unroll
    for (int i = 0; i < 32; i += 8) {
        int n = n0 + ty + i, k = k0 + tx;
        bf16 h, l; split2(tile[tx][ty + i], h, l);
        oh[(size_t)n * KP + k] = h; ol[(size_t)n * KP + k] = l;
    }
}

// merged W1/W2/W3 transpose+split, z selects target. grid (16,16,3), block (32,8)
__global__ void conv_W(const float* __restrict__ W1, const float* __restrict__ W2,
                       const float* __restrict__ W3) {
    int z = blockIdx.z;
    if (z == 0) {
        if (blockIdx.x >= K1P / 32) return;
        conv_T_body(W1, g_W1h, g_W1l, Dd + 1, Hh, Hh, K1P);
    } else if (z == 1) {
        conv_T_body(W2, g_W2h, g_W2l, Hh, Hh, Hh, Hh);
    } else {
        if (blockIdx.y >= 4) return;
        conv_T_body(W3, g_W3h, g_W3l, Hh, Dd, Dd, Hh);
    }
}

// A0 = concat([xs, t], pad to 128) -> bf16 hi/lo
__global__ void conv_A0(const float* __restrict__ xs, const float* __restrict__ t,
                        bf16* __restrict__ ah, bf16* __restrict__ al) {
    int i = blockIdx.x * 256 + threadIdx.x;
    int b = i >> 7, k = i & 127;
    float v = (k < Dd) ? xs[b * Dd + k] : ((k == Dd) ? t[b] : 0.f);
    bf16 h, l; split2(v, h, l);
    ah[i] = h; al[i] = l;
}

// ---------------- tcgen05 GEMM ----------------------------------------------
// D[128x128] = A[128xK] @ B^T via 2-term bf16 split (Ah.Bh + Ah.Bl + Al.Bh).
// MODE 0: silu epilogue -> o0h/o0l, o1h/o1l (bf16)                   (layer 1)
// MODE 1: silu epilogue -> o0h/o0l (bf16), of32 = silu' (fp32)       (layer 2)
// MODE 2: K-split partial (blockIdx.x = K quarter), cols<66 -> dpart (layer 3)
// MODE 3: row-dot with s2f -> dpart                                  (u / div)
#define IDESC 0x8200490u
#define STAGEB 65536
#define T16K   16384
#define SMEM_SZ 133120

template<int MODE>
__global__ void __launch_bounds__(256, 1)
mma_gemm(const bf16* __restrict__ Ah, const bf16* __restrict__ Al,
         const bf16* __restrict__ Bh, const bf16* __restrict__ Bl,
         const float* __restrict__ bias,
         bf16* __restrict__ o0h, bf16* __restrict__ o0l,
         bf16* __restrict__ o1h, bf16* __restrict__ o1l,
         float* __restrict__ of32, const float* __restrict__ s2f,
         float* __restrict__ dpart, int KA, int KB, int NC)
{
#if HAS_TCGEN05
    extern __shared__ char smc[];
    const uint32_t up0 = smem_u32(smc);
    const uint32_t tb  = (up0 + 1024u) & ~1023u;     // 1024-aligned tile base
    char* tilec = smc + (tb - up0);
    const uint32_t mb0 = up0 + 8;
    const uint32_t mb1 = up0 + 16;

    const int tid = threadIdx.x;
    const int wid = tid >> 5;
    const int rowBase = blockIdx.y * 128;
    const int colBase = (MODE == 2) ? 0 : blockIdx.x * 128;
    const int kbase   = (MODE == 2) ? blockIdx.x * NC : 0;   // chunk offset (K-split)

    if (wid == 0) { TCALLOC(up0, 128u); TCRELINQ(); }
    if (tid == 0) { MBINIT(mb0, 1u); MBINIT(mb1, 1u); }
    __syncthreads();
    uint32_t tmem;
    asm volatile("ld.shared.b32 %0, [%1];" : "=r"(tmem) : "r"(up0));

    const int r    = tid >> 1;          // 0..127 (A row / B row)
    const int half = tid & 1;           // which 64B half of the 128B row

    // ---- load chunk 0 into stage 0
    {
        const size_t ko = (size_t)kbase * 64 + half * 32;
        const bf16* pa_h = Ah + (size_t)(rowBase + r) * KA + ko;
        const bf16* pa_l = Al + (size_t)(rowBase + r) * KA + ko;
        const bf16* pb_h = Bh + (size_t)(colBase + r) * KB + ko;
        const bf16* pb_l = Bl + (size_t)(colBase + r) * KB + ko;
        uint32_t off = (uint32_t)r * 128 + half * 64;
#pragma unroll
        for (int q = 0; q < 4; q++) {
            uint32_t so = sw128(off + q * 16);
            *(uint4*)(tilec + 0 * T16K + so) = *(const uint4*)(pa_h + q * 8);
            *(uint4*)(tilec + 1 * T16K + so) = *(const uint4*)(pa_l + q * 8);
            *(uint4*)(tilec + 2 * T16K + so) = *(const uint4*)(pb_h + q * 8);
            *(uint4*)(tilec + 3 * T16K + so) = *(const uint4*)(pb_l + q * 8);
        }
    }
    FENCE_ASYNC();
    __syncthreads();

    for (int c = 0; c < NC; c++) {
        const uint32_t st = c & 1;
        if (wid == 0 && elect_one()) {
            uint32_t ab = tb + st * STAGEB;
            uint64_t dAh = mkdesc(ab), dAl = mkdesc(ab + T16K);
            uint64_t dBh = mkdesc(ab + 2 * T16K), dBl = mkdesc(ab + 3 * T16K);
            uint32_t en = (c == 0) ? 0u : 1u;
#pragma unroll
            for (int k = 0; k < 4; k++) {
                mma_bf16_ss(tmem, dAh + 2 * k, dBh + 2 * k, IDESC, en); en = 1u;
                mma_bf16_ss(tmem, dAh + 2 * k, dBl + 2 * k, IDESC, 1u);
                mma_bf16_ss(tmem, dAl + 2 * k, dBh + 2 * k, IDESC, 1u);
            }
            TCCOMMIT(st ? mb1 : mb0);
        }
        if (c + 1 < NC) {
            const size_t ko = (size_t)(kbase + c + 1) * 64 + half * 32;
            const bf16* pa_h = Ah + (size_t)(rowBase + r) * KA + ko;
            const bf16* pa_l = Al + (size_t)(rowBase + r) * KA + ko;
            const bf16* pb_h = Bh + (size_t)(colBase + r) * KB + ko;
            const bf16* pb_l = Bl + (size_t)(colBase + r) * KB + ko;
            uint4 va[4], vb[4], vc[4], vd[4];
#pragma unroll
            for (int q = 0; q < 4; q++) {
                va[q] = *(const uint4*)(pa_h + q * 8);
                vb[q] = *(const uint4*)(pa_l + q * 8);
                vc[q] = *(const uint4*)(pb_h + q * 8);
                vd[q] = *(const uint4*)(pb_l + q * 8);
            }
            const uint32_t nxt = (c + 1) & 1;
            if (c >= 1) mbar_wait(nxt ? mb1 : mb0, (uint32_t)(((c - 1) >> 1) & 1));
            char* nb = tilec + nxt * STAGEB;
            uint32_t off = (uint32_t)r * 128 + half * 64;
#pragma unroll
            for (int q = 0; q < 4; q++) {
                uint32_t so = sw128(off + q * 16);
                *(uint4*)(nb + 0 * T16K + so) = va[q];
                *(uint4*)(nb + 1 * T16K + so) = vb[q];
                *(uint4*)(nb + 2 * T16K + so) = vc[q];
                *(uint4*)(nb + 3 * T16K + so) = vd[q];
            }
            FENCE_ASYNC();
        }
        __syncthreads();
    }
    mbar_wait(((NC - 1) & 1) ? mb1 : mb0, (uint32_t)(((NC - 1) >> 1) & 1));
    TCFENCE_AFTER();
    __syncthreads();

    // ---- MODE 3: stage s2 tile into smem (MMA done; smem free) -------------
    float* s2s = (float*)tilec;                    // [128][129] = 66048 B
    float* rs  = (float*)(tilec + 66560);          // cross-warpgroup partials
    if (MODE == 3) {
        for (int i = tid; i < 128 * 128; i += 256) {
            int rr = i >> 7, cc = i & 127;
            s2s[rr * 129 + cc] = s2f[(size_t)(rowBase + rr) * Hh + colBase + cc];
        }
        __syncthreads();
    }

    // ---- epilogue: ALL 8 warps read D; warpgroup eg takes column half -------
    {
        const int erow = tid & 127;               // row within tile (subpart = wid%4)
        const int eg   = tid >> 7;                // 0: cols 0-63, 1: cols 64-127
        const int gr   = rowBase + erow;
        float rsum = 0.f;
#pragma unroll
        for (int chi = 0; chi < 2; chi++) {
            const int ch = eg * 2 + chi;
            if (MODE == 2 && ch >= 3) continue;   // cols >= 96 unused (Dd=66)
            uint32_t regs[32];
            LDTM32(regs, tmem + ch * 32);
            TCWAIT_LD();
            const int gcB = colBase + ch * 32;
            if (MODE == 0 || MODE == 1) {
#pragma unroll
                for (int cc = 0; cc < 32; cc += 2) {
                    float x0 = __uint_as_float(regs[cc])     + bias[gcB + cc];
                    float x1 = __uint_as_float(regs[cc + 1]) + bias[gcB + cc + 1];
                    float sg0 = 1.f / (1.f + __expf(-x0));
                    float sg1 = 1.f / (1.f + __expf(-x1));
                    float hh0 = x0 * sg0, hh1 = x1 * sg1;
                    float dd0 = sg0 * (1.f + x0 * (1.f - sg0));
                    float dd1 = sg1 * (1.f + x1 * (1.f - sg1));
                    size_t o = (size_t)gr * Hh + gcB + cc;
                    __nv_bfloat162 ph, pl;
                    bf16 th, tl;
                    split2(hh0, th, tl); ph.x = th; pl.x = tl;
                    split2(hh1, th, tl); ph.y = th; pl.y = tl;
                    *(__nv_bfloat162*)&o0h[o] = ph;
                    *(__nv_bfloat162*)&o0l[o] = pl;
                    if (MODE == 0) {
                        split2(dd0, th, tl); ph.x = th; pl.x = tl;
                        split2(dd1, th, tl); ph.y = th; pl.y = tl;
                        *(__nv_bfloat162*)&o1h[o] = ph;
                        *(__nv_bfloat162*)&o1l[o] = pl;
                    } else {
                        *(float2*)&of32[o] = make_float2(dd0, dd1);
                    }
                }
            } else if (MODE == 2) {
#pragma unroll
                for (int cc = 0; cc < 32; cc++) {
                    int gc = gcB + cc;
                    if (gc < Dd)
                        dpart[((size_t)blockIdx.x * Bsz + gr) * Dd + gc] =
                            __uint_as_float(regs[cc]);
                }
            } else {  // MODE 3
#pragma unroll
                for (int cc = 0; cc < 32; cc++)
                    rsum = fmaf(__uint_as_float(regs[cc]),
                                s2s[erow * 129 + ch * 32 + cc], rsum);
            }
        }
        if (MODE == 3) {
            __syncthreads();
            if (eg == 1) rs[erow] = rsum;
            __syncthreads();
            if (eg == 0) dpart[blockIdx.x * Bsz + gr] = rsum + rs[erow];
        }
        TCFENCE_BEFORE();
    }
    __syncthreads();
    if (wid == 0) TCDEALLOC(tmem, 128u);
#endif  // HAS_TCGEN05
}

// fused: dxs = sum of 4 layer-3 K-partials + b3;  -div = -(sum of 4 dp partials)
__global__ void finish(const float* __restrict__ l3p, const float* __restrict__ b3,
                       const float* __restrict__ dp, float* __restrict__ out) {
    const int total = Bsz * Dd;
    int idx = blockIdx.x * 256 + threadIdx.x;
    if (idx < total) {
        out[idx] = l3p[idx] + l3p[total + idx] + l3p[2 * total + idx]
                 + l3p[3 * total + idx] + b3[idx % Dd];
    } else if (idx < total + Bsz) {
        int b = idx - total;
        out[total + b] = -(dp[b] + dp[Bsz + b] + dp[2 * Bsz + b] + dp[3 * Bsz + b]);
    }
}

// ---------------- launch -----------------------------------------------------
extern "C" void kernel_launch(void* const* d_in, const int* in_sizes, int n_in,
                              void* d_out, int out_size) {
    const float* xs = (const float*)d_in[0];
    const float* t  = (const float*)d_in[1];
    const float* W1 = (const float*)d_in[2];
    const float* b1 = (const float*)d_in[3];
    const float* W2 = (const float*)d_in[4];
    const float* b2 = (const float*)d_in[5];
    const float* W3 = (const float*)d_in[6];
    const float* b3 = (const float*)d_in[7];
    float* out = (float*)d_out;

    bf16 *A0h,*A0l,*W1h,*W1l,*W2h,*W2l,*W3h,*W3l,*Chb,*Clb;
    bf16 *h1h,*h1l,*s1h,*s1l,*h2h,*h2l;
    float *s2, *dp, *l3p;
    cudaGetSymbolAddress((void**)&A0h, g_A0h); cudaGetSymbolAddress((void**)&A0l, g_A0l);
    cudaGetSymbolAddress((void**)&W1h, g_W1h); cudaGetSymbolAddress((void**)&W1l, g_W1l);
    cudaGetSymbolAddress((void**)&W2h, g_W2h); cudaGetSymbolAddress((void**)&W2l, g_W2l);
    cudaGetSymbolAddress((void**)&W3h, g_W3h); cudaGetSymbolAddress((void**)&W3l, g_W3l);
    cudaGetSymbolAddress((void**)&Chb, g_Chb); cudaGetSymbolAddress((void**)&Clb, g_Clb);
    cudaGetSymbolAddress((void**)&h1h, g_h1h); cudaGetSymbolAddress((void**)&h1l, g_h1l);
    cudaGetSymbolAddress((void**)&s1h, g_s1h); cudaGetSymbolAddress((void**)&s1l, g_s1l);
    cudaGetSymbolAddress((void**)&h2h, g_h2h); cudaGetSymbolAddress((void**)&h2l, g_h2l);
    cudaGetSymbolAddress((void**)&s2,  g_s2);
    cudaGetSymbolAddress((void**)&dp,  g_dp);
    cudaGetSymbolAddress((void**)&l3p, g_l3p);

    cudaFuncSetAttribute(mma_gemm<0>, cudaFuncAttributeMaxDynamicSharedMemorySize, SMEM_SZ);
    cudaFuncSetAttribute(mma_gemm<1>, cudaFuncAttributeMaxDynamicSharedMemorySize, SMEM_SZ);
    cudaFuncSetAttribute(mma_gemm<2>, cudaFuncAttributeMaxDynamicSharedMemorySize, SMEM_SZ);
    cudaFuncSetAttribute(mma_gemm<3>, cudaFuncAttributeMaxDynamicSharedMemorySize, SMEM_SZ);

    // prep: 3 launches
    prep_C<<<dim3(16, 16), dim3(32, 8)>>>(W1, W2, W3, Chb, Clb);          // #1
    conv_A0<<<(Bsz * K1P) / 256, 256>>>(xs, t, A0h, A0l);                 // #2
    conv_W<<<dim3(16, 16, 3), dim3(32, 8)>>>(W1, W2, W3);                 // #3

    // layer 1: [xs|t] @ W1 -> h1(hi/lo), s1(hi/lo)
    mma_gemm<0><<<dim3(4, 32), 256, SMEM_SZ>>>(A0h, A0l, W1h, W1l, b1,    // #4
        h1h, h1l, s1h, s1l, nullptr, nullptr, nullptr, K1P, K1P, 2);
    // layer 2: h1 @ W2 -> h2(hi/lo), s2(fp32)
    mma_gemm<1><<<dim3(4, 32), 256, SMEM_SZ>>>(h1h, h1l, W2h, W2l, b2,    // #5
        h2h, h2l, nullptr, nullptr, s2, nullptr, nullptr, Hh, Hh, 8);
    // u = s1 @ C fused with row-dot(s2) -> dp partials   (launch #6 -> ncu target)
    mma_gemm<3><<<dim3(4, 32), 256, SMEM_SZ>>>(s1h, s1l, Chb, Clb, nullptr, // #6
        nullptr, nullptr, nullptr, nullptr, nullptr, s2, dp, Hh, Hh, 8);
    // layer 3 (K-split x4): h2 @ W3 partials -> l3p
    mma_gemm<2><<<dim3(4, 32), 256, SMEM_SZ>>>(h2h, h2l, W3h, W3l, nullptr, // #7
        nullptr, nullptr, nullptr, nullptr, nullptr, nullptr, l3p, Hh, Hh, 2);
    // combine: dxs + bias, -div
    finish<<<(Bsz * Dd + Bsz + 255) / 256, 256>>>(l3p, b3, dp, out);      // #8
}

// round 14
// speedup vs baseline: 2.3767x; 2.3767x over previous
#include <cuda_runtime.h>
#include <cuda_bf16.h>
#include <cstdint>

#define Bsz 4096
#define Dd  66
#define Hh  512
#define K1P 128      // padded K for layer 1 (66 + 1 + zeros)

// tcgen05 is arch-specific: only emit it in the sm_103a (or sm_100a) pass.
#if defined(__CUDA_ARCH_FEAT_SM103_ALL) || defined(__CUDA_ARCH_FEAT_SM100_ALL) || \
    (defined(__CUDA_ARCH_SPECIFIC__) && defined(__CUDA_ARCH__) && (__CUDA_ARCH__ >= 1000))
#define HAS_TCGEN05 1
#else
#define HAS_TCGEN05 0
#endif

typedef __nv_bfloat16 bf16;

// ---------------- scratch (__device__ globals; allocation-free rule) ---------
__device__ bf16  g_A0h[Bsz*K1P], g_A0l[Bsz*K1P];
__device__ bf16  g_W1h[Hh*K1P],  g_W1l[Hh*K1P];     // W1^T padded [512 x 128]
__device__ bf16  g_W2h[Hh*Hh],   g_W2l[Hh*Hh];      // W2^T [512 x 512]
__device__ bf16  g_W3h[128*Hh],  g_W3l[128*Hh];     // W3^T padded [128 x 512]
__device__ bf16  g_Chb[Hh*Hh],   g_Clb[Hh*Hh];      // C^T  [512 x 512]
__device__ bf16  g_h1h[Bsz*Hh],  g_h1l[Bsz*Hh];
__device__ bf16  g_s1h[Bsz*Hh],  g_s1l[Bsz*Hh];
__device__ bf16  g_h2h[Bsz*Hh],  g_h2l[Bsz*Hh];
__device__ float g_s2[Bsz*Hh];
__device__ float g_dp[4*Bsz];
__device__ float g_l3p[4*Bsz*Dd];   // layer-3 K-split partials

// ---------------- helpers ----------------------------------------------------
__device__ __forceinline__ uint32_t smem_u32(const void* p) {
    uint32_t a;
    asm("{ .reg .u64 t; cvta.to.shared.u64 t, %1; cvt.u32.u64 %0, t; }" : "=r"(a) : "l"(p));
    return a;
}
__device__ __forceinline__ uint32_t sw128(uint32_t o) { return o ^ ((o >> 3) & 0x70); }
__device__ __forceinline__ void split2(float v, bf16& h, bf16& l) {
    h = __float2bfloat16(v);
    l = __float2bfloat16(v - __bfloat162float(h));
}

#if HAS_TCGEN05
__device__ __forceinline__ uint32_t elect_one() {
    uint32_t p;
    asm volatile("{\n\t.reg .pred p;\n\telect.sync _|p, 0xFFFFFFFF;\n\t"
                 "selp.b32 %0, 1, 0, p;\n\t}" : "=r"(p));
    return p;
}
__device__ __forceinline__ uint64_t mkdesc(uint32_t addr) {
    // SW128, version=1(Blackwell), SBO=64, LBO=1
    return 0x4000404000010000ull | ((uint64_t)(addr >> 4) & 0x3FFF);
}
__device__ __forceinline__ void mma_bf16_ss(uint32_t d, uint64_t ad, uint64_t bd,
                                            uint32_t idesc, uint32_t en) {
    asm volatile("{\n\t.reg .pred p;\n\tsetp.ne.u32 p, %4, 0;\n\t"
        "tcgen05.mma.cta_group::1.kind::f16 [%0], %1, %2, %3, {%5,%5,%5,%5}, p;\n\t}"
        :: "r"(d), "l"(ad), "l"(bd), "r"(idesc), "r"(en), "r"(0u) : "memory");
}
#define TCALLOC(sp, n)  asm volatile("tcgen05.alloc.cta_group::1.sync.aligned.shared::cta.b32 [%0], %1;" :: "r"(sp), "r"(n) : "memory")
#define TCDEALLOC(t, n) asm volatile("tcgen05.dealloc.cta_group::1.sync.aligned.b32 %0, %1;" :: "r"(t), "r"(n))
#define TCRELINQ()      asm volatile("tcgen05.relinquish_alloc_permit.cta_group::1.sync.aligned;")
#define TCCOMMIT(mb)    asm volatile("tcgen05.commit.cta_group::1.mbarrier::arrive::one.shared::cluster.b64 [%0];" :: "r"(mb) : "memory")
#define MBINIT(mb, n)   asm volatile("mbarrier.init.shared.b64 [%0], %1;" :: "r"(mb), "r"(n) : "memory")
#define FENCE_ASYNC()   asm volatile("fence.proxy.async.shared::cta;" ::: "memory")
#define TCFENCE_AFTER() asm volatile("tcgen05.fence::after_thread_sync;" ::: "memory")
#define TCFENCE_BEFORE() asm volatile("tcgen05.fence::before_thread_sync;" ::: "memory")
#define TCWAIT_LD()     asm volatile("tcgen05.wait::ld.sync.aligned;" ::: "memory")
#define EGBAR(eg)       asm volatile("bar.sync %0, 128;" :: "r"(1 + (eg)) : "memory")

__device__ __forceinline__ void mbar_wait(uint32_t mb, uint32_t parity) {
    uint32_t done;
    asm volatile("{\n\t.reg .pred p;\n\t"
        "mbarrier.try_wait.parity.acquire.cta.shared::cta.b64 p, [%1], %2;\n\t"
        "selp.b32 %0, 1, 0, p;\n\t}" : "=r"(done) : "r"(mb), "r"(parity) : "memory");
    if (!done) {
        asm volatile("{\n\t.reg .pred P1;\n\tWL_%=:\n\t"
            "mbarrier.try_wait.parity.acquire.cta.shared::cta.b64 P1, [%0], %1, 0x989680;\n\t"
            "@P1 bra.uni WD_%=;\n\tbra.uni WL_%=;\n\tWD_%=:\n\t}"
            :: "r"(mb), "r"(parity) : "memory");
    }
}
#define LDTM32(r, a) \
    asm volatile("tcgen05.ld.sync.aligned.32x32b.x32.b32 " \
        "{%0,%1,%2,%3,%4,%5,%6,%7,%8,%9,%10,%11,%12,%13,%14,%15," \
        "%16,%17,%18,%19,%20,%21,%22,%23,%24,%25,%26,%27,%28,%29,%30,%31}, [%32];" \
        : "=r"((r)[0]),"=r"((r)[1]),"=r"((r)[2]),"=r"((r)[3]),"=r"((r)[4]),"=r"((r)[5]), \
          "=r"((r)[6]),"=r"((r)[7]),"=r"((r)[8]),"=r"((r)[9]),"=r"((r)[10]),"=r"((r)[11]), \
          "=r"((r)[12]),"=r"((r)[13]),"=r"((r)[14]),"=r"((r)[15]),"=r"((r)[16]),"=r"((r)[17]), \
          "=r"((r)[18]),"=r"((r)[19]),"=r"((r)[20]),"=r"((r)[21]),"=r"((r)[22]),"=r"((r)[23]), \
          "=r"((r)[24]),"=r"((r)[25]),"=r"((r)[26]),"=r"((r)[27]),"=r"((r)[28]),"=r"((r)[29]), \
          "=r"((r)[30]),"=r"((r)[31]) : "r"(a))
#endif  // HAS_TCGEN05

// ---------------- prep kernels ----------------------------------------------
__global__ void prep_C(const float* __restrict__ W1, const float* __restrict__ W2,
                       const float* __restrict__ W3,
                       bf16* __restrict__ Chb, bf16* __restrict__ Clb) {
    __shared__ float W2s[32][33];
    __shared__ float W3s[32][Dd];
    const int i0 = blockIdx.x * 32, j0 = blockIdx.y * 32;
    const int tx = threadIdx.x, ty = threadIdx.y;
#pragma unroll
    for (int r = 0; r < 4; r++)
        W2s[ty * 4 + r][tx] = W2[(size_t)(i0 + ty * 4 + r) * Hh + j0 + tx];
    for (int e = ty * 32 + tx; e < 32 * Dd; e += 256)
        W3s[e / Dd][e % Dd] = W3[(size_t)(j0 + e / Dd) * Dd + e % Dd];
    __syncthreads();
#pragma unroll
    for (int q = 0; q < 4; q++) {
        const int jl = ty * 4 + q;
        float acc = 0.f;
#pragma unroll
        for (int d = 0; d < Dd; d++)
            acc = fmaf(W3s[jl][d], W1[(size_t)d * Hh + i0 + tx], acc);
        float cv = W2s[tx][jl] * acc;
        bf16 h, l; split2(cv, h, l);
        Chb[(size_t)(j0 + jl) * Hh + i0 + tx] = h;
        Clb[(size_t)(j0 + jl) * Hh + i0 + tx] = l;
    }
}

__device__ __forceinline__ void conv_T_body(const float* __restrict__ W,
                                            bf16* __restrict__ oh, bf16* __restrict__ ol,
                                            int KS, int NS, int NW, int KP) {
    __shared__ float tile[32][33];
    int k0 = blockIdx.x * 32, n0 = blockIdx.y * 32;
    int tx = threadIdx.x, ty = threadIdx.y;
#pragma unroll
    for (int i = 0; i < 32; i += 8) {
        int k = k0 + ty + i, n = n0 + tx;
        tile[ty + i][tx] = (k < KS && n < NS) ? W[(size_t)k * NW + n] : 0.f;
    }
    __syncthreads();
#pragma unroll
    for (int i = 0; i < 32; i += 8) {
        int n = n0 + ty + i, k = k0 + tx;
        bf16 h, l; split2(tile[tx][ty + i], h, l);
        oh[(size_t)n * KP + k] = h; ol[(size_t)n * KP + k] = l;
    }
}

__global__ void conv_W(const float* __restrict__ W1, const float* __restrict__ W2,
                       const float* __restrict__ W3) {
    int z = blockIdx.z;
    if (z == 0) {
        if (blockIdx.x >= K1P / 32) return;
        conv_T_body(W1, g_W1h, g_W1l, Dd + 1, Hh, Hh, K1P);
    } else if (z == 1) {
        conv_T_body(W2, g_W2h, g_W2l, Hh, Hh, Hh, Hh);
    } else {
        if (blockIdx.y >= 4) return;
        conv_T_body(W3, g_W3h, g_W3l, Hh, Dd, Dd, Hh);
    }
}

__global__ void conv_A0(const float* __restrict__ xs, const float* __restrict__ t,
                        bf16* __restrict__ ah, bf16* __restrict__ al) {
    int i = blockIdx.x * 256 + threadIdx.x;
    int b = i >> 7, k = i & 127;
    float v = (k < Dd) ? xs[b * Dd + k] : ((k == Dd) ? t[b] : 0.f);
    bf16 h, l; split2(v, h, l);
    ah[i] = h; al[i] = l;
}

// ---------------- tcgen05 GEMM ----------------------------------------------
// D[128x128] = A[128xK] @ B^T via 2-term bf16 split (Ah.Bh + Ah.Bl + Al.Bh).
// MODE 0: silu epilogue -> o0h/o0l, o1h/o1l (bf16)                   (layer 1)
// MODE 1: silu epilogue -> o0h/o0l (bf16), of32 = silu' (fp32)       (layer 2)
// MODE 2: K-split partial (blockIdx.x = K quarter), cols<66 -> dpart (layer 3)
// MODE 3: row-dot with s2f -> dpart                                  (u / div)
#define IDESC 0x8200490u
#define STAGEB 65536
#define T16K   16384
#define SMEM_SZ 133120

template<int MODE>
__global__ void __launch_bounds__(256, 1)
mma_gemm(const bf16* __restrict__ Ah, const bf16* __restrict__ Al,
         const bf16* __restrict__ Bh, const bf16* __restrict__ Bl,
         const float* __restrict__ bias,
         bf16* __restrict__ o0h, bf16* __restrict__ o0l,
         bf16* __restrict__ o1h, bf16* __restrict__ o1l,
         float* __restrict__ of32, const float* __restrict__ s2f,
         float* __restrict__ dpart, int KA, int KB, int NC)
{
#if HAS_TCGEN05
    extern __shared__ char smc[];
    const uint32_t up0 = smem_u32(smc);
    const uint32_t tb  = (up0 + 1024u) & ~1023u;     // 1024-aligned tile base
    char* tilec = smc + (tb - up0);
    const uint32_t mb0 = up0 + 8;
    const uint32_t mb1 = up0 + 16;

    const int tid = threadIdx.x;
    const int wid = tid >> 5;
    const int rowBase = blockIdx.y * 128;
    const int colBase = (MODE == 2) ? 0 : blockIdx.x * 128;
    const int kbase   = (MODE == 2) ? blockIdx.x * NC : 0;   // chunk offset (K-split)

    if (wid == 0) { TCALLOC(up0, 128u); TCRELINQ(); }
    if (tid == 0) { MBINIT(mb0, 1u); MBINIT(mb1, 1u); }
    __syncthreads();
    uint32_t tmem;
    asm volatile("ld.shared.b32 %0, [%1];" : "=r"(tmem) : "r"(up0));

    // coalesced load mapping: warp w covers rows w*4..w*4+3 (+q*32), 8 lanes x
    // 16B = full 128B row -> 4x128B coalesced transactions per LDG.128.
    const int L = tid & 31, w = tid >> 5;
    const int rbase4 = w * 4 + (L >> 3);
    const int lslot  = L & 7;                  // 16B slot within 128B row

    // ---- load chunk 0 into stage 0
    {
        const size_t ko = (size_t)kbase * 64 + lslot * 8;
#pragma unroll
        for (int q = 0; q < 4; q++) {
            const int row = rbase4 + q * 32;
            const uint32_t so = sw128((uint32_t)row * 128 + lslot * 16);
            *(uint4*)(tilec + 0 * T16K + so) = *(const uint4*)(Ah + (size_t)(rowBase + row) * KA + ko);
            *(uint4*)(tilec + 1 * T16K + so) = *(const uint4*)(Al + (size_t)(rowBase + row) * KA + ko);
            *(uint4*)(tilec + 2 * T16K + so) = *(const uint4*)(Bh + (size_t)(colBase + row) * KB + ko);
            *(uint4*)(tilec + 3 * T16K + so) = *(const uint4*)(Bl + (size_t)(colBase + row) * KB + ko);
        }
    }
    FENCE_ASYNC();
    __syncthreads();

    for (int c = 0; c < NC; c++) {
        const uint32_t st = c & 1;
        if (wid == 0 && elect_one()) {
            uint32_t ab = tb + st * STAGEB;
            uint64_t dAh = mkdesc(ab), dAl = mkdesc(ab + T16K);
            uint64_t dBh = mkdesc(ab + 2 * T16K), dBl = mkdesc(ab + 3 * T16K);
            uint32_t en = (c == 0) ? 0u : 1u;
#pragma unroll
            for (int k = 0; k < 4; k++) {
                mma_bf16_ss(tmem, dAh + 2 * k, dBh + 2 * k, IDESC, en); en = 1u;
                mma_bf16_ss(tmem, dAh + 2 * k, dBl + 2 * k, IDESC, 1u);
                mma_bf16_ss(tmem, dAl + 2 * k, dBh + 2 * k, IDESC, 1u);
            }
            TCCOMMIT(st ? mb1 : mb0);
        }
        if (c + 1 < NC) {
            const size_t ko = (size_t)(kbase + c + 1) * 64 + lslot * 8;
            uint4 va[4], vb[4], vc[4], vd[4];
#pragma unroll
            for (int q = 0; q < 4; q++) {
                const int row = rbase4 + q * 32;
                va[q] = *(const uint4*)(Ah + (size_t)(rowBase + row) * KA + ko);
                vb[q] = *(const uint4*)(Al + (size_t)(rowBase + row) * KA + ko);
                vc[q] = *(const uint4*)(Bh + (size_t)(colBase + row) * KB + ko);
                vd[q] = *(const uint4*)(Bl + (size_t)(colBase + row) * KB + ko);
            }
            const uint32_t nxt = (c + 1) & 1;
            if (c >= 1) mbar_wait(nxt ? mb1 : mb0, (uint32_t)(((c - 1) >> 1) & 1));
            char* nb = tilec + nxt * STAGEB;
#pragma unroll
            for (int q = 0; q < 4; q++) {
                const int row = rbase4 + q * 32;
                const uint32_t so = sw128((uint32_t)row * 128 + lslot * 16);
                *(uint4*)(nb + 0 * T16K + so) = va[q];
                *(uint4*)(nb + 1 * T16K + so) = vb[q];
                *(uint4*)(nb + 2 * T16K + so) = vc[q];
                *(uint4*)(nb + 3 * T16K + so) = vd[q];
            }
            FENCE_ASYNC();
        }
        __syncthreads();
    }
    mbar_wait(((NC - 1) & 1) ? mb1 : mb0, (uint32_t)(((NC - 1) >> 1) & 1));
    TCFENCE_AFTER();
    __syncthreads();

    // ---- MODE 3: stage s2 tile into smem (MMA done; smem free) -------------
    float* s2s = (float*)tilec;                    // [128][129] = 66048 B
    float* rs  = (float*)(tilec + 66560);          // cross-warpgroup partials
    if (MODE == 3) {
        for (int i = tid; i < 128 * 128; i += 256) {
            int rr = i >> 7, cc = i & 127;
            s2s[rr * 129 + cc] = s2f[(size_t)(rowBase + rr) * Hh + colBase + cc];
        }
        __syncthreads();
    }

    // ---- epilogue: 8 warps; eg = column half. Stores staged via smem with
    //      conflict-free strides, then coalesced copy-out. -------------------
    {
        const int erow = tid & 127;               // row (subpartition = wid%4)
        const int eg   = tid >> 7;                // 0: cols 0-63, 1: cols 64-127
        const int gr   = rowBase + erow;
        const int t2   = tid & 127;
        uint32_t* stg = (uint32_t*)tilec;
        // bf16 chunk buffers (uint32=bf16x2): [128][17] words each
        uint32_t* bb[4] = { stg + (0 * 2 + eg) * 128 * 17, stg + (1 * 2 + eg) * 128 * 17,
                            stg + (2 * 2 + eg) * 128 * 17, stg + (3 * 2 + eg) * 128 * 17 };
        // fp32 chunk buffer: [128][33] words
        float* fb = (MODE == 1) ? (float*)(stg + 4 * 128 * 17) + eg * 128 * 33
                                : (float*)stg + eg * 128 * 33;
        float rsum = 0.f;

#pragma unroll
        for (int chi = 0; chi < 2; chi++) {
            const int ch = eg * 2 + chi;
            if (MODE == 2 && ch >= 3) continue;   // cols >= 96 unused (Dd=66)
            uint32_t regs[32];
            LDTM32(regs, tmem + ch * 32);
            TCWAIT_LD();
            const int gcB = colBase + ch * 32;

            if (MODE == 0 || MODE == 1) {
#pragma unroll
                for (int cc = 0; cc < 32; cc += 2) {
                    float x0 = __uint_as_float(regs[cc])     + bias[gcB + cc];
                    float x1 = __uint_as_float(regs[cc + 1]) + bias[gcB + cc + 1];
                    float sg0 = 1.f / (1.f + __expf(-x0));
                    float sg1 = 1.f / (1.f + __expf(-x1));
                    float hh0 = x0 * sg0, hh1 = x1 * sg1;
                    float dd0 = sg0 * (1.f + x0 * (1.f - sg0));
                    float dd1 = sg1 * (1.f + x1 * (1.f - sg1));
                    __nv_bfloat162 ph, pl; bf16 th, tl;
                    split2(hh0, th, tl); ph.x = th; pl.x = tl;
                    split2(hh1, th, tl); ph.y = th; pl.y = tl;
                    bb[0][erow * 17 + (cc >> 1)] = *(uint32_t*)&ph;
                    bb[1][erow * 17 + (cc >> 1)] = *(uint32_t*)&pl;
                    if (MODE == 0) {
                        split2(dd0, th, tl); ph.x = th; pl.x = tl;
                        split2(dd1, th, tl); ph.y = th; pl.y = tl;
                        bb[2][erow * 17 + (cc >> 1)] = *(uint32_t*)&ph;
                        bb[3][erow * 17 + (cc >> 1)] = *(uint32_t*)&pl;
                    } else {
                        fb[erow * 33 + cc] = dd0;
                        fb[erow * 33 + cc + 1] = dd1;
                    }
                }
                EGBAR(eg);
                // coalesced copy-out: warp covers 8 rows x 64B per iteration
                bf16* outs[4] = { o0h, o0l, o1h, o1l };
                const int NB = (MODE == 0) ? 4 : 2;
                for (int ob = 0; ob < NB; ob++) {
                    uint32_t* src = bb[ob];
                    bf16* dst = outs[ob];
#pragma unroll
                    for (int i = 0; i < 4; i++) {
                        int row = i * 32 + (t2 >> 2);
                        int sl  = t2 & 3;
                        uint32_t* s = src + row * 17 + sl * 4;
                        uint4 v = make_uint4(s[0], s[1], s[2], s[3]);
                        *(uint4*)(dst + (size_t)(rowBase + row) * Hh + gcB + sl * 8) = v;
                    }
                }
                if (MODE == 1) {
#pragma unroll
                    for (int i = 0; i < 4; i++) {
                        int row = i * 32 + (t2 >> 2);
                        int sl  = t2 & 3;
                        float* s = fb + row * 33 + sl * 8;
                        float* d = of32 + (size_t)(rowBase + row) * Hh + gcB + sl * 8;
                        *(float4*)d       = make_float4(s[0], s[1], s[2], s[3]);
                        *(float4*)(d + 4) = make_float4(s[4], s[5], s[6], s[7]);
                    }
                }
                EGBAR(eg);
            } else if (MODE == 2) {
#pragma unroll
                for (int cc = 0; cc < 32; cc++)
                    fb[erow * 33 + cc] = __uint_as_float(regs[cc]);
                EGBAR(eg);
                const int vc = (ch == 2) ? 2 : 32;
                for (int idx = t2; idx < 128 * vc; idx += 128) {
                    int row, col;
                    if (vc == 32) { row = idx >> 5; col = idx & 31; }
                    else          { row = idx >> 1; col = idx & 1;  }
                    dpart[((size_t)blockIdx.x * Bsz + rowBase + row) * Dd + ch * 32 + col]
                        = fb[row * 33 + col];
                }
                EGBAR(eg);
            } else {  // MODE 3
#pragma unroll
                for (int cc = 0; cc < 32; cc++)
                    rsum = fmaf(__uint_as_float(regs[cc]),
                                s2s[erow * 129 + ch * 32 + cc], rsum);
            }
        }
        if (MODE == 3) {
            __syncthreads();
            if (eg == 1) rs[erow] = rsum;
            __syncthreads();
            if (eg == 0) dpart[blockIdx.x * Bsz + gr] = rsum + rs[erow];
        }
        TCFENCE_BEFORE();
    }
    __syncthreads();
    if (wid == 0) TCDEALLOC(tmem, 128u);
#endif  // HAS_TCGEN05
}

// fused: dxs = sum of 4 layer-3 K-partials + b3;  -div = -(sum of 4 dp partials)
__global__ void finish(const float* __restrict__ l3p, const float* __restrict__ b3,
                       const float* __restrict__ dp, float* __restrict__ out) {
    const int total = Bsz * Dd;
    int idx = blockIdx.x * 256 + threadIdx.x;
    if (idx < total) {
        out[idx] = l3p[idx] + l3p[total + idx] + l3p[2 * total + idx]
                 + l3p[3 * total + idx] + b3[idx % Dd];
    } else if (idx < total + Bsz) {
        int b = idx - total;
        out[total + b] = -(dp[b] + dp[Bsz + b] + dp[2 * Bsz + b] + dp[3 * Bsz + b]);
    }
}

// ---------------- launch -----------------------------------------------------
extern "C" void kernel_launch(void* const* d_in, const int* in_sizes, int n_in,
                              void* d_out, int out_size) {
    const float* xs = (const float*)d_in[0];
    const float* t  = (const float*)d_in[1];
    const float* W1 = (const float*)d_in[2];
    const float* b1 = (const float*)d_in[3];
    const float* W2 = (const float*)d_in[4];
    const float* b2 = (const float*)d_in[5];
    const float* W3 = (const float*)d_in[6];
    const float* b3 = (const float*)d_in[7];
    float* out = (float*)d_out;

    bf16 *A0h,*A0l,*W1h,*W1l,*W2h,*W2l,*W3h,*W3l,*Chb,*Clb;
    bf16 *h1h,*h1l,*s1h,*s1l,*h2h,*h2l;
    float *s2, *dp, *l3p;
    cudaGetSymbolAddress((void**)&A0h, g_A0h); cudaGetSymbolAddress((void**)&A0l, g_A0l);
    cudaGetSymbolAddress((void**)&W1h, g_W1h); cudaGetSymbolAddress((void**)&W1l, g_W1l);
    cudaGetSymbolAddress((void**)&W2h, g_W2h); cudaGetSymbolAddress((void**)&W2l, g_W2l);
    cudaGetSymbolAddress((void**)&W3h, g_W3h); cudaGetSymbolAddress((void**)&W3l, g_W3l);
    cudaGetSymbolAddress((void**)&Chb, g_Chb); cudaGetSymbolAddress((void**)&Clb, g_Clb);
    cudaGetSymbolAddress((void**)&h1h, g_h1h); cudaGetSymbolAddress((void**)&h1l, g_h1l);
    cudaGetSymbolAddress((void**)&s1h, g_s1h); cudaGetSymbolAddress((void**)&s1l, g_s1l);
    cudaGetSymbolAddress((void**)&h2h, g_h2h); cudaGetSymbolAddress((void**)&h2l, g_h2l);
    cudaGetSymbolAddress((void**)&s2,  g_s2);
    cudaGetSymbolAddress((void**)&dp,  g_dp);
    cudaGetSymbolAddress((void**)&l3p, g_l3p);

    cudaFuncSetAttribute(mma_gemm<0>, cudaFuncAttributeMaxDynamicSharedMemorySize, SMEM_SZ);
    cudaFuncSetAttribute(mma_gemm<1>, cudaFuncAttributeMaxDynamicSharedMemorySize, SMEM_SZ);
    cudaFuncSetAttribute(mma_gemm<2>, cudaFuncAttributeMaxDynamicSharedMemorySize, SMEM_SZ);
    cudaFuncSetAttribute(mma_gemm<3>, cudaFuncAttributeMaxDynamicSharedMemorySize, SMEM_SZ);

    // prep: 3 launches
    prep_C<<<dim3(16, 16), dim3(32, 8)>>>(W1, W2, W3, Chb, Clb);          // #1
    conv_A0<<<(Bsz * K1P) / 256, 256>>>(xs, t, A0h, A0l);                 // #2
    conv_W<<<dim3(16, 16, 3), dim3(32, 8)>>>(W1, W2, W3);                 // #3

    // layer 1: [xs|t] @ W1 -> h1(hi/lo), s1(hi/lo)
    mma_gemm<0><<<dim3(4, 32), 256, SMEM_SZ>>>(A0h, A0l, W1h, W1l, b1,    // #4
        h1h, h1l, s1h, s1l, nullptr, nullptr, nullptr, K1P, K1P, 2);
    // layer 2: h1 @ W2 -> h2(hi/lo), s2(fp32)
    mma_gemm<1><<<dim3(4, 32), 256, SMEM_SZ>>>(h1h, h1l, W2h, W2l, b2,    // #5
        h2h, h2l, nullptr, nullptr, s2, nullptr, nullptr, Hh, Hh, 8);
    // u = s1 @ C fused with row-dot(s2) -> dp partials
    mma_gemm<3><<<dim3(4, 32), 256, SMEM_SZ>>>(s1h, s1l, Chb, Clb, nullptr, // #6
        nullptr, nullptr, nullptr, nullptr, nullptr, s2, dp, Hh, Hh, 8);
    // layer 3 (K-split x4): h2 @ W3 partials -> l3p
    mma_gemm<2><<<dim3(4, 32), 256, SMEM_SZ>>>(h2h, h2l, W3h, W3l, nullptr, // #7
        nullptr, nullptr, nullptr, nullptr, nullptr, nullptr, l3p, Hh, Hh, 2);
    // combine: dxs + bias, -div
    finish<<<(Bsz * Dd + Bsz + 255) / 256, 256>>>(l3p, b3, dp, out);      // #8
}

// round 15
// speedup vs baseline: 2.9186x; 1.2280x over previous
#include <cuda_runtime.h>
#include <cuda_bf16.h>
#include <cstdint>

#define Bsz 4096
#define Dd  66
#define Hh  512
#define K1P 128      // padded K for layer 1 (66 + 1 + zeros)

// tcgen05 is arch-specific: only emit it in the sm_103a (or sm_100a) pass.
#if defined(__CUDA_ARCH_FEAT_SM103_ALL) || defined(__CUDA_ARCH_FEAT_SM100_ALL) || \
    (defined(__CUDA_ARCH_SPECIFIC__) && defined(__CUDA_ARCH__) && (__CUDA_ARCH__ >= 1000))
#define HAS_TCGEN05 1
#else
#define HAS_TCGEN05 0
#endif

typedef __nv_bfloat16 bf16;

// ---- tiled-global format: 16KB tiles = exact smem image (sw128 swizzled) ----
// tile(nb, c) holds rows nb*128..+127, k-chunk c (64 bf16), inner offset
// sw128((n&127)*128 + (k&63)*2). fp32 s2 tiles: 32KB, 64 cols, XOR-swizzled.

// ---------------- scratch (__device__ globals; allocation-free rule) ---------
__device__ bf16  g_A0h[Bsz*K1P], g_A0l[Bsz*K1P];
__device__ bf16  g_W1h[Hh*K1P],  g_W1l[Hh*K1P];
__device__ bf16  g_W2h[Hh*Hh],   g_W2l[Hh*Hh];
__device__ bf16  g_W3h[128*Hh],  g_W3l[128*Hh];
__device__ bf16  g_Chb[Hh*Hh],   g_Clb[Hh*Hh];
__device__ bf16  g_h1h[Bsz*Hh],  g_h1l[Bsz*Hh];
__device__ bf16  g_s1h[Bsz*Hh],  g_s1l[Bsz*Hh];
__device__ bf16  g_h2h[Bsz*Hh],  g_h2l[Bsz*Hh];
__device__ float g_s2[Bsz*Hh];      // tiled fp32 (32KB tiles)
__device__ float g_dp[4*Bsz];
__device__ float g_l3p[4*Bsz*Dd];

// ---------------- helpers ----------------------------------------------------
__device__ __forceinline__ uint32_t smem_u32(const void* p) {
    uint32_t a;
    asm("{ .reg .u64 t; cvta.to.shared.u64 t, %1; cvt.u32.u64 %0, t; }" : "=r"(a) : "l"(p));
    return a;
}
__device__ __forceinline__ uint32_t sw128(uint32_t o) { return o ^ ((o >> 3) & 0x70); }
__device__ __forceinline__ void split2(float v, bf16& h, bf16& l) {
    h = __float2bfloat16(v);
    l = __float2bfloat16(v - __bfloat162float(h));
}
// byte address of element (n, k) in bf16 tiled layout with nc k-chunks
__device__ __forceinline__ size_t tadr(int n, int k, int nc) {
    uint32_t inner = sw128((((uint32_t)n & 127u) << 7) + (((uint32_t)k & 63u) << 1));
    return ((((size_t)(n >> 7)) * nc + (size_t)(k >> 6)) << 14) + inner;
}

#if HAS_TCGEN05
__device__ __forceinline__ uint32_t elect_one() {
    uint32_t p;
    asm volatile("{\n\t.reg .pred p;\n\telect.sync _|p, 0xFFFFFFFF;\n\t"
                 "selp.b32 %0, 1, 0, p;\n\t}" : "=r"(p));
    return p;
}
__device__ __forceinline__ uint64_t mkdesc(uint32_t addr) {
    return 0x4000404000010000ull | ((uint64_t)(addr >> 4) & 0x3FFF);
}
__device__ __forceinline__ void mma_bf16_ss(uint32_t d, uint64_t ad, uint64_t bd,
                                            uint32_t idesc, uint32_t en) {
    asm volatile("{\n\t.reg .pred p;\n\tsetp.ne.u32 p, %4, 0;\n\t"
        "tcgen05.mma.cta_group::1.kind::f16 [%0], %1, %2, %3, {%5,%5,%5,%5}, p;\n\t}"
        :: "r"(d), "l"(ad), "l"(bd), "r"(idesc), "r"(en), "r"(0u) : "memory");
}
#define TCALLOC(sp, n)  asm volatile("tcgen05.alloc.cta_group::1.sync.aligned.shared::cta.b32 [%0], %1;" :: "r"(sp), "r"(n) : "memory")
#define TCDEALLOC(t, n) asm volatile("tcgen05.dealloc.cta_group::1.sync.aligned.b32 %0, %1;" :: "r"(t), "r"(n))
#define TCRELINQ()      asm volatile("tcgen05.relinquish_alloc_permit.cta_group::1.sync.aligned;")
#define TCCOMMIT(mb)    asm volatile("tcgen05.commit.cta_group::1.mbarrier::arrive::one.shared::cluster.b64 [%0];" :: "r"(mb) : "memory")
#define MBINIT(mb, n)   asm volatile("mbarrier.init.shared.b64 [%0], %1;" :: "r"(mb), "r"(n) : "memory")
#define MBEXPECT(mb, n) asm volatile("mbarrier.arrive.expect_tx.shared.b64 _, [%0], %1;" :: "r"(mb), "r"(n) : "memory")
#define FENCE_ASYNC()   asm volatile("fence.proxy.async.shared::cta;" ::: "memory")
#define TCFENCE_AFTER() asm volatile("tcgen05.fence::after_thread_sync;" ::: "memory")
#define TCFENCE_BEFORE() asm volatile("tcgen05.fence::before_thread_sync;" ::: "memory")
#define TCWAIT_LD()     asm volatile("tcgen05.wait::ld.sync.aligned;" ::: "memory")
#define EGBAR(eg)       asm volatile("bar.sync %0, 128;" :: "r"(1 + (eg)) : "memory")
#define BULK_G2S(dst, src, bytes, mb) \
    asm volatile("cp.async.bulk.shared::cluster.global.mbarrier::complete_tx::bytes [%0], [%1], %2, [%3];" \
        :: "r"(dst), "l"(src), "r"(bytes), "r"(mb) : "memory")
#define BULK_S2G(dst, src, bytes) \
    asm volatile("cp.async.bulk.global.shared::cta.bulk_group [%0], [%1], %2;" \
        :: "l"(dst), "r"(src), "r"(bytes) : "memory")
#define BULK_COMMIT() asm volatile("cp.async.bulk.commit_group;" ::: "memory")
#define BULK_WAIT0()  asm volatile("cp.async.bulk.wait_group 0;" ::: "memory")

__device__ __forceinline__ void mbar_wait(uint32_t mb, uint32_t parity) {
    uint32_t done;
    asm volatile("{\n\t.reg .pred p;\n\t"
        "mbarrier.try_wait.parity.acquire.cta.shared::cta.b64 p, [%1], %2;\n\t"
        "selp.b32 %0, 1, 0, p;\n\t}" : "=r"(done) : "r"(mb), "r"(parity) : "memory");
    if (!done) {
        asm volatile("{\n\t.reg .pred P1;\n\tWL_%=:\n\t"
            "mbarrier.try_wait.parity.acquire.cta.shared::cta.b64 P1, [%0], %1, 0x989680;\n\t"
            "@P1 bra.uni WD_%=;\n\tbra.uni WL_%=;\n\tWD_%=:\n\t}"
            :: "r"(mb), "r"(parity) : "memory");
    }
}
#define LDTM32(r, a) \
    asm volatile("tcgen05.ld.sync.aligned.32x32b.x32.b32 " \
        "{%0,%1,%2,%3,%4,%5,%6,%7,%8,%9,%10,%11,%12,%13,%14,%15," \
        "%16,%17,%18,%19,%20,%21,%22,%23,%24,%25,%26,%27,%28,%29,%30,%31}, [%32];" \
        : "=r"((r)[0]),"=r"((r)[1]),"=r"((r)[2]),"=r"((r)[3]),"=r"((r)[4]),"=r"((r)[5]), \
          "=r"((r)[6]),"=r"((r)[7]),"=r"((r)[8]),"=r"((r)[9]),"=r"((r)[10]),"=r"((r)[11]), \
          "=r"((r)[12]),"=r"((r)[13]),"=r"((r)[14]),"=r"((r)[15]),"=r"((r)[16]),"=r"((r)[17]), \
          "=r"((r)[18]),"=r"((r)[19]),"=r"((r)[20]),"=r"((r)[21]),"=r"((r)[22]),"=r"((r)[23]), \
          "=r"((r)[24]),"=r"((r)[25]),"=r"((r)[26]),"=r"((r)[27]),"=r"((r)[28]),"=r"((r)[29]), \
          "=r"((r)[30]),"=r"((r)[31]) : "r"(a))
#endif  // HAS_TCGEN05

// ---------------- prep kernels (write tiled-swizzled layout) ------------------
__global__ void prep_C(const float* __restrict__ W1, const float* __restrict__ W2,
                       const float* __restrict__ W3,
                       bf16* __restrict__ Chb, bf16* __restrict__ Clb) {
    __shared__ float W2s[32][33];
    __shared__ float W3s[32][Dd];
    const int i0 = blockIdx.x * 32, j0 = blockIdx.y * 32;
    const int tx = threadIdx.x, ty = threadIdx.y;
#pragma unroll
    for (int r = 0; r < 4; r++)
        W2s[ty * 4 + r][tx] = W2[(size_t)(i0 + ty * 4 + r) * Hh + j0 + tx];
    for (int e = ty * 32 + tx; e < 32 * Dd; e += 256)
        W3s[e / Dd][e % Dd] = W3[(size_t)(j0 + e / Dd) * Dd + e % Dd];
    __syncthreads();
#pragma unroll
    for (int q = 0; q < 4; q++) {
        const int jl = ty * 4 + q;
        float acc = 0.f;
#pragma unroll
        for (int d = 0; d < Dd; d++)
            acc = fmaf(W3s[jl][d], W1[(size_t)d * Hh + i0 + tx], acc);
        float cv = W2s[tx][jl] * acc;
        bf16 h, l; split2(cv, h, l);
        size_t a = tadr(j0 + jl, i0 + tx, 8);
        *(bf16*)((char*)Chb + a) = h;
        *(bf16*)((char*)Clb + a) = l;
    }
}

__device__ __forceinline__ void conv_T_body(const float* __restrict__ W,
                                            bf16* __restrict__ oh, bf16* __restrict__ ol,
                                            int KS, int NS, int NW, int nc) {
    __shared__ float tile[32][33];
    int k0 = blockIdx.x * 32, n0 = blockIdx.y * 32;
    int tx = threadIdx.x, ty = threadIdx.y;
#pragma unroll
    for (int i = 0; i < 32; i += 8) {
        int k = k0 + ty + i, n = n0 + tx;
        tile[ty + i][tx] = (k < KS && n < NS) ? W[(size_t)k * NW + n] : 0.f;
    }
    __syncthreads();
#pragma unroll
    for (int i = 0; i < 32; i += 8) {
        int n = n0 + ty + i, k = k0 + tx;
        bf16 h, l; split2(tile[tx][ty + i], h, l);
        size_t a = tadr(n, k, nc);
        *(bf16*)((char*)oh + a) = h;
        *(bf16*)((char*)ol + a) = l;
    }
}

__global__ void conv_W(const float* __restrict__ W1, const float* __restrict__ W2,
                       const float* __restrict__ W3) {
    int z = blockIdx.z;
    if (z == 0) {
        if (blockIdx.x >= K1P / 32) return;
        conv_T_body(W1, g_W1h, g_W1l, Dd + 1, Hh, Hh, 2);
    } else if (z == 1) {
        conv_T_body(W2, g_W2h, g_W2l, Hh, Hh, Hh, 8);
    } else {
        if (blockIdx.y >= 4) return;
        conv_T_body(W3, g_W3h, g_W3l, Hh, Dd, Dd, 8);
    }
}

__global__ void conv_A0(const float* __restrict__ xs, const float* __restrict__ t,
                        bf16* __restrict__ ah, bf16* __restrict__ al) {
    int i = blockIdx.x * 256 + threadIdx.x;
    int b = i >> 7, k = i & 127;
    float v = (k < Dd) ? xs[b * Dd + k] : ((k == Dd) ? t[b] : 0.f);
    bf16 h, l; split2(v, h, l);
    size_t a = tadr(b, k, 2);
    *(bf16*)((char*)ah + a) = h;
    *(bf16*)((char*)al + a) = l;
}

// ---------------- tcgen05 GEMM (bulk-copy fed) -------------------------------
// MODE 0: silu -> h1(hi/lo), s1(hi/lo) bf16 tiles                    (layer 1)
// MODE 1: silu -> h2(hi/lo) bf16 tiles, s2 fp32 tiles                (layer 2)
// MODE 2: K-split partial, cols<66 -> dpart (plain layout)           (layer 3)
// MODE 3: row-dot with tiled s2 -> dpart                             (u / div)
#define IDESC 0x8200490u
#define STAGEB 65536
#define T16K   16384
#define SMEM_SZ 133120

template<int MODE>
__global__ void __launch_bounds__(256, 1)
mma_gemm(const bf16* __restrict__ Ah, const bf16* __restrict__ Al,
         const bf16* __restrict__ Bh, const bf16* __restrict__ Bl,
         const float* __restrict__ bias,
         bf16* __restrict__ o0h, bf16* __restrict__ o0l,
         bf16* __restrict__ o1h, bf16* __restrict__ o1l,
         float* __restrict__ of32, const float* __restrict__ s2f,
         float* __restrict__ dpart, int ncA, int ncB, int NC)
{
#if HAS_TCGEN05
    extern __shared__ char smc[];
    const uint32_t up0 = smem_u32(smc);
    const uint32_t tb  = (up0 + 1536u) & ~1023u;
    char* tilec = smc + (tb - up0);
    const uint32_t mld0 = up0 + 8,  mld1 = up0 + 16;
    const uint32_t mmm0 = up0 + 24, mmm1 = up0 + 32;
    const uint32_t ms2  = up0 + 40;

    const int tid = threadIdx.x;
    const int wid = tid >> 5;
    const int bx = blockIdx.x, by = blockIdx.y;
    const int rowBase = by * 128;
    const int colBase = (MODE == 2) ? 0 : bx * 128;
    const int kbase   = (MODE == 2) ? bx * NC : 0;
    const int bxB     = (MODE == 2) ? 0 : bx;

    if (wid == 0) { TCALLOC(up0, 128u); TCRELINQ(); }
    if (tid == 0) { MBINIT(mld0, 1u); MBINIT(mld1, 1u);
                    MBINIT(mmm0, 1u); MBINIT(mmm1, 1u); MBINIT(ms2, 1u); }
    __syncthreads();
    uint32_t tmem;
    asm volatile("ld.shared.b32 %0, [%1];" : "=r"(tmem) : "r"(up0));

    // ---- single-thread mainloop: bulk loads + MMAs, mbarrier-pipelined ------
    if (wid == 0 && elect_one()) {
        // issue chunk 0 into stage 0
        MBEXPECT(mld0, 65536u);
        {
            size_t ta = (((size_t)by * ncA + kbase) << 14);
            size_t tbo = (((size_t)bxB * ncB + kbase) << 14);
            BULK_G2S(tb + 0 * T16K, (const char*)Ah + ta,  16384u, mld0);
            BULK_G2S(tb + 1 * T16K, (const char*)Al + ta,  16384u, mld0);
            BULK_G2S(tb + 2 * T16K, (const char*)Bh + tbo, 16384u, mld0);
            BULK_G2S(tb + 3 * T16K, (const char*)Bl + tbo, 16384u, mld0);
        }
        for (int c = 0; c < NC; c++) {
            const uint32_t st = c & 1;
            if (c + 1 < NC) {
                const uint32_t nxt = st ^ 1;
                if (c >= 1) mbar_wait(nxt ? mmm1 : mmm0, (uint32_t)(((c - 1) >> 1) & 1));
                MBEXPECT(nxt ? mld1 : mld0, 65536u);
                size_t ta = (((size_t)by * ncA + kbase + c + 1) << 14);
                size_t tbo = (((size_t)bxB * ncB + kbase + c + 1) << 14);
                uint32_t d = tb + nxt * STAGEB;
                BULK_G2S(d + 0 * T16K, (const char*)Ah + ta,  16384u, nxt ? mld1 : mld0);
                BULK_G2S(d + 1 * T16K, (const char*)Al + ta,  16384u, nxt ? mld1 : mld0);
                BULK_G2S(d + 2 * T16K, (const char*)Bh + tbo, 16384u, nxt ? mld1 : mld0);
                BULK_G2S(d + 3 * T16K, (const char*)Bl + tbo, 16384u, nxt ? mld1 : mld0);
            }
            mbar_wait(st ? mld1 : mld0, (uint32_t)((c >> 1) & 1));
            uint32_t ab = tb + st * STAGEB;
            uint64_t dAh = mkdesc(ab), dAl = mkdesc(ab + T16K);
            uint64_t dBh = mkdesc(ab + 2 * T16K), dBl = mkdesc(ab + 3 * T16K);
            uint32_t en = (c == 0) ? 0u : 1u;
#pragma unroll
            for (int k = 0; k < 4; k++) {
                mma_bf16_ss(tmem, dAh + 2 * k, dBh + 2 * k, IDESC, en); en = 1u;
                mma_bf16_ss(tmem, dAh + 2 * k, dBl + 2 * k, IDESC, 1u);
                mma_bf16_ss(tmem, dAl + 2 * k, dBh + 2 * k, IDESC, 1u);
            }
            TCCOMMIT(st ? mmm1 : mmm0);
        }
        mbar_wait(((NC - 1) & 1) ? mmm1 : mmm0, (uint32_t)(((NC - 1) >> 1) & 1));
        if (MODE == 3) {   // bulk-load the two 32KB s2 tiles (stages now free)
            MBEXPECT(ms2, 65536u);
            BULK_G2S(tb,          (const char*)s2f + (((size_t)by * 8 + bx * 2 + 0) << 15), 32768u, ms2);
            BULK_G2S(tb + 32768u, (const char*)s2f + (((size_t)by * 8 + bx * 2 + 1) << 15), 32768u, ms2);
        }
    }
    __syncthreads();
    TCFENCE_AFTER();
    if (MODE == 3) mbar_wait(ms2, 0u);

    // ---- epilogue -----------------------------------------------------------
    const int erow = tid & 127;
    const int eg   = tid >> 7;            // 0: cols 0-63, 1: cols 64-127

    if (MODE == 0 || MODE == 1) {
        char* ebase = tilec + eg * STAGEB;
        uint32_t ebu = tb + eg * STAGEB;
        const int c_out = bx * 2 + eg;
#pragma unroll
        for (int chi = 0; chi < 2; chi++) {
            const int ch = eg * 2 + chi;
            uint32_t regs[32];
            LDTM32(regs, tmem + ch * 32);
            TCWAIT_LD();
            const int gcB = colBase + ch * 32;
#pragma unroll
            for (int cc = 0; cc < 32; cc += 2) {
                float x0 = __uint_as_float(regs[cc])     + bias[gcB + cc];
                float x1 = __uint_as_float(regs[cc + 1]) + bias[gcB + cc + 1];
                float sg0 = 1.f / (1.f + __expf(-x0));
                float sg1 = 1.f / (1.f + __expf(-x1));
                float hh0 = x0 * sg0, hh1 = x1 * sg1;
                float dd0 = sg0 * (1.f + x0 * (1.f - sg0));
                float dd1 = sg1 * (1.f + x1 * (1.f - sg1));
                const uint32_t off = sw128(((uint32_t)erow << 7) + (uint32_t)((chi * 32 + cc) << 1));
                __nv_bfloat162 ph, pl; bf16 th, tl;
                split2(hh0, th, tl); ph.x = th; pl.x = tl;
                split2(hh1, th, tl); ph.y = th; pl.y = tl;
                *(uint32_t*)(ebase + 0 * T16K + off) = *(uint32_t*)&ph;
                *(uint32_t*)(ebase + 1 * T16K + off) = *(uint32_t*)&pl;
                if (MODE == 0) {
                    split2(dd0, th, tl); ph.x = th; pl.x = tl;
                    split2(dd1, th, tl); ph.y = th; pl.y = tl;
                    *(uint32_t*)(ebase + 2 * T16K + off) = *(uint32_t*)&ph;
                    *(uint32_t*)(ebase + 3 * T16K + off) = *(uint32_t*)&pl;
                } else {
                    const int cl = chi * 32 + cc;
                    uint32_t fo = (uint32_t)erow * 256 + (((uint32_t)cl * 4) ^ (((uint32_t)erow & 7) << 4));
                    *(float2*)(ebase + 2 * T16K + fo) = make_float2(dd0, dd1);
                }
            }
        }
        EGBAR(eg);
        if ((tid & 127) == 0) {
            FENCE_ASYNC();
            size_t to = ((size_t)by * 8 + c_out) << 14;
            BULK_S2G((char*)o0h + to, ebu + 0 * T16K, 16384u);
            BULK_S2G((char*)o0l + to, ebu + 1 * T16K, 16384u);
            if (MODE == 0) {
                BULK_S2G((char*)o1h + to, ebu + 2 * T16K, 16384u);
                BULK_S2G((char*)o1l + to, ebu + 3 * T16K, 16384u);
            } else {
                BULK_S2G((char*)of32 + (((size_t)by * 8 + c_out) << 15), ebu + 2 * T16K, 32768u);
            }
            BULK_COMMIT(); BULK_WAIT0();
        }
        EGBAR(eg);
    } else if (MODE == 2) {
        float* fb = (float*)tilec + eg * (128 * 33);
#pragma unroll
        for (int chi = 0; chi < 2; chi++) {
            const int ch = eg * 2 + chi;
            if (ch >= 3) continue;
            uint32_t regs[32];
            LDTM32(regs, tmem + ch * 32);
            TCWAIT_LD();
#pragma unroll
            for (int cc = 0; cc < 32; cc++)
                fb[erow * 33 + cc] = __uint_as_float(regs[cc]);
            EGBAR(eg);
            const int vc = (ch == 2) ? 2 : 32;
            for (int idx = (tid & 127); idx < 128 * vc; idx += 128) {
                int row, col;
                if (vc == 32) { row = idx >> 5; col = idx & 31; }
                else          { row = idx >> 1; col = idx & 1;  }
                dpart[((size_t)bx * Bsz + rowBase + row) * Dd + ch * 32 + col]
                    = fb[row * 33 + col];
            }
            EGBAR(eg);
        }
    } else {  // MODE 3
        const char* sbase = tilec + eg * 32768;
        float rsum = 0.f;
#pragma unroll
        for (int chi = 0; chi < 2; chi++) {
            const int ch = eg * 2 + chi;
            uint32_t regs[32];
            LDTM32(regs, tmem + ch * 32);
            TCWAIT_LD();
#pragma unroll
            for (int cc = 0; cc < 32; cc++) {
                const int cl = chi * 32 + cc;
                float sv = *(const float*)(sbase + (uint32_t)erow * 256 +
                            (((uint32_t)cl * 4) ^ (((uint32_t)erow & 7) << 4)));
                rsum = fmaf(__uint_as_float(regs[cc]), sv, rsum);
            }
        }
        float* rs = (float*)(tilec + STAGEB);
        __syncthreads();
        if (eg == 1) rs[erow] = rsum;
        __syncthreads();
        if (eg == 0) dpart[bx * Bsz + rowBase + erow] = rsum + rs[erow];
    }
    TCFENCE_BEFORE();
    __syncthreads();
    if (wid == 0) TCDEALLOC(tmem, 128u);
#endif  // HAS_TCGEN05
}

// fused: dxs = sum of 4 layer-3 K-partials + b3;  -div = -(sum of 4 dp partials)
__global__ void finish(const float* __restrict__ l3p, const float* __restrict__ b3,
                       const float* __restrict__ dp, float* __restrict__ out) {
    const int total = Bsz * Dd;
    int idx = blockIdx.x * 256 + threadIdx.x;
    if (idx < total) {
        out[idx] = l3p[idx] + l3p[total + idx] + l3p[2 * total + idx]
                 + l3p[3 * total + idx] + b3[idx % Dd];
    } else if (idx < total + Bsz) {
        int b = idx - total;
        out[total + b] = -(dp[b] + dp[Bsz + b] + dp[2 * Bsz + b] + dp[3 * Bsz + b]);
    }
}

// ---------------- launch -----------------------------------------------------
extern "C" void kernel_launch(void* const* d_in, const int* in_sizes, int n_in,
                              void* d_out, int out_size) {
    const float* xs = (const float*)d_in[0];
    const float* t  = (const float*)d_in[1];
    const float* W1 = (const float*)d_in[2];
    const float* b1 = (const float*)d_in[3];
    const float* W2 = (const float*)d_in[4];
    const float* b2 = (const float*)d_in[5];
    const float* W3 = (const float*)d_in[6];
    const float* b3 = (const float*)d_in[7];
    float* out = (float*)d_out;

    bf16 *A0h,*A0l,*W1h,*W1l,*W2h,*W2l,*W3h,*W3l,*Chb,*Clb;
    bf16 *h1h,*h1l,*s1h,*s1l,*h2h,*h2l;
    float *s2, *dp, *l3p;
    cudaGetSymbolAddress((void**)&A0h, g_A0h); cudaGetSymbolAddress((void**)&A0l, g_A0l);
    cudaGetSymbolAddress((void**)&W1h, g_W1h); cudaGetSymbolAddress((void**)&W1l, g_W1l);
    cudaGetSymbolAddress((void**)&W2h, g_W2h); cudaGetSymbolAddress((void**)&W2l, g_W2l);
    cudaGetSymbolAddress((void**)&W3h, g_W3h); cudaGetSymbolAddress((void**)&W3l, g_W3l);
    cudaGetSymbolAddress((void**)&Chb, g_Chb); cudaGetSymbolAddress((void**)&Clb, g_Clb);
    cudaGetSymbolAddress((void**)&h1h, g_h1h); cudaGetSymbolAddress((void**)&h1l, g_h1l);
    cudaGetSymbolAddress((void**)&s1h, g_s1h); cudaGetSymbolAddress((void**)&s1l, g_s1l);
    cudaGetSymbolAddress((void**)&h2h, g_h2h); cudaGetSymbolAddress((void**)&h2l, g_h2l);
    cudaGetSymbolAddress((void**)&s2,  g_s2);
    cudaGetSymbolAddress((void**)&dp,  g_dp);
    cudaGetSymbolAddress((void**)&l3p, g_l3p);

    cudaFuncSetAttribute(mma_gemm<0>, cudaFuncAttributeMaxDynamicSharedMemorySize, SMEM_SZ);
    cudaFuncSetAttribute(mma_gemm<1>, cudaFuncAttributeMaxDynamicSharedMemorySize, SMEM_SZ);
    cudaFuncSetAttribute(mma_gemm<2>, cudaFuncAttributeMaxDynamicSharedMemorySize, SMEM_SZ);
    cudaFuncSetAttribute(mma_gemm<3>, cudaFuncAttributeMaxDynamicSharedMemorySize, SMEM_SZ);

    // prep
    prep_C<<<dim3(16, 16), dim3(32, 8)>>>(W1, W2, W3, Chb, Clb);          // #1
    conv_A0<<<(Bsz * K1P) / 256, 256>>>(xs, t, A0h, A0l);                 // #2
    conv_W<<<dim3(16, 16, 3), dim3(32, 8)>>>(W1, W2, W3);                 // #3

    // layer 1: [xs|t] @ W1 -> h1(hi/lo), s1(hi/lo)
    mma_gemm<0><<<dim3(4, 32), 256, SMEM_SZ>>>(A0h, A0l, W1h, W1l, b1,    // #4
        h1h, h1l, s1h, s1l, nullptr, nullptr, nullptr, 2, 2, 2);
    // layer 2: h1 @ W2 -> h2(hi/lo), s2 (fp32 tiles)
    mma_gemm<1><<<dim3(4, 32), 256, SMEM_SZ>>>(h1h, h1l, W2h, W2l, b2,    // #5
        h2h, h2l, nullptr, nullptr, s2, nullptr, nullptr, 8, 8, 8);
    // u = s1 @ C fused with row-dot(s2) -> dp partials   (ncu target, #6)
    mma_gemm<3><<<dim3(4, 32), 256, SMEM_SZ>>>(s1h, s1l, Chb, Clb, nullptr, // #6
        nullptr, nullptr, nullptr, nullptr, nullptr, s2, dp, 8, 8, 8);
    // layer 3 (K-split x4): h2 @ W3 partials -> l3p
    mma_gemm<2><<<dim3(4, 32), 256, SMEM_SZ>>>(h2h, h2l, W3h, W3l, nullptr, // #7
        nullptr, nullptr, nullptr, nullptr, nullptr, nullptr, l3p, 8, 8, 2);
    // combine: dxs + bias, -div
    finish<<<(Bsz * Dd + Bsz + 255) / 256, 256>>>(l3p, b3, dp, out);      // #8
}